// round 9
// baseline (speedup 1.0000x reference)
#include <cuda_runtime.h>

#define HH 512
#define WW 512
#define BATCH 16
#define RPB 8        // rows per block (= threadIdx.y range)
#define PXT 16       // pixels per thread along x
#define TX 32        // threads in x (TX*PXT = 512)
#define TILE_W 516   // 512 + 2 halo each side
#define TILE_STRIDE 520
#define TILE_H (RPB + 4)      // 12
#define NTHREADS (TX * RPB)   // 256

__device__ __forceinline__ void ce(float& a, float& b) {
    float t = fminf(a, b);
    b = fmaxf(a, b);
    a = t;
}

// optimal 9-CE sorting network for 5 elements
__device__ __forceinline__ void sort5(float v[5]) {
    ce(v[0], v[1]); ce(v[3], v[4]); ce(v[2], v[4]);
    ce(v[2], v[3]); ce(v[0], v[3]); ce(v[0], v[2]);
    ce(v[1], v[4]); ce(v[1], v[3]); ce(v[1], v[2]);
}

// Batcher odd-even merge of two sorted 5-lists -> sorted 10-list (13 CE)
__device__ __forceinline__ void merge55(const float x[5], const float y[5], float z[10]) {
    float t0 = fminf(x[0], y[0]), t1 = fmaxf(x[0], y[0]);
    float w0 = fminf(x[4], y[4]), w1 = fmaxf(x[4], y[4]);
    float r1 = fminf(w0, t1),     r2 = fmaxf(w0, t1);
    float s0 = fminf(x[2], y[2]), s1 = fmaxf(x[2], y[2]);
    float p0 = t0;
    float p1 = fminf(s0, r1), p2 = fmaxf(s0, r1);
    float p3 = fminf(s1, r2), p4 = fmaxf(s1, r2);
    float p5 = w1;
    float a0 = fminf(x[1], y[1]), a1 = fmaxf(x[1], y[1]);
    float b0 = fminf(x[3], y[3]), b1 = fmaxf(x[3], y[3]);
    float q0 = a0;
    float q1 = fminf(b0, a1), q2 = fmaxf(b0, a1);
    float q3 = b1;
    z[0] = p0;
    z[1] = fminf(q0, p1); z[2] = fmaxf(q0, p1);
    z[3] = fminf(q1, p2); z[4] = fmaxf(q1, p2);
    z[5] = fminf(q2, p3); z[6] = fmaxf(q2, p3);
    z[7] = fminf(q3, p4); z[8] = fmaxf(q3, p4);
    z[9] = p5;
}

// Pruned OEM(10,10): ranks 7..12 (s[0]=s7 ... s[5]=s12) of the merged 20-list.
__device__ __forceinline__ void prune_mid(const float m1[10], const float m2[10], float s[6]) {
    float t1  = fmaxf(m1[0], m2[0]);
    float w0  = fminf(m1[8], m2[8]);
    float r1  = fminf(w0, t1),  r2 = fmaxf(w0, t1);
    float s0  = fminf(m1[4], m2[4]), s1 = fmaxf(m1[4], m2[4]);
    float p2  = fmaxf(s0, r1),  p3 = fminf(s1, r2);
    float t1q = fmaxf(m1[2], m2[2]);
    float w0q = fminf(m1[6], m2[6]);
    float q1  = fminf(w0q, t1q), q2 = fmaxf(w0q, t1q);
    float d4  = fmaxf(q1, p2);
    float d5  = fminf(q2, p3), d6 = fmaxf(q2, p3);

    float t1g = fmaxf(m1[1], m2[1]);
    float w0g = fminf(m1[9], m2[9]);
    float r1g = fminf(w0g, t1g), r2g = fmaxf(w0g, t1g);
    float s0g = fminf(m1[5], m2[5]), s1g = fmaxf(m1[5], m2[5]);
    float p2g = fmaxf(s0g, r1g), p3g = fminf(s1g, r2g);
    float t1h = fmaxf(m1[3], m2[3]);
    float w0h = fminf(m1[7], m2[7]);
    float q1g = fminf(w0h, t1h), q2g = fmaxf(w0h, t1h);
    float g3  = fminf(q1g, p2g), g4 = fmaxf(q1g, p2g);
    float g5  = fminf(q2g, p3g);

    s[0] = fminf(g3, d4); s[1] = fmaxf(g3, d4);
    s[2] = fminf(g4, d5); s[3] = fmaxf(g4, d5);
    s[4] = fminf(g5, d6); s[5] = fmaxf(g5, d6);
}

// 13th smallest of S(20) U E(5), tree-shaped.
__device__ __forceinline__ float sel13(const float s[6], const float E[5]) {
    float a = fmaxf(s[4], E[0]);
    float b = fmaxf(s[3], E[1]);
    float c = fmaxf(s[2], E[2]);
    float d = fmaxf(s[1], E[3]);
    float e = fmaxf(s[0], E[4]);
    return fminf(fminf(fminf(a, b), fminf(c, d)), fminf(e, s[5]));
}

__device__ __forceinline__ float sum5(const float v[5]) {
    return ((v[0] + v[1]) + (v[2] + v[3])) + v[4];
}
__device__ __forceinline__ float sq5(const float v[5]) {
    return fmaf(v[0], v[0], fmaf(v[1], v[1], fmaf(v[2], v[2], fmaf(v[3], v[3], v[4] * v[4]))));
}

__global__ __launch_bounds__(NTHREADS, 3)
void Net_29291676958726_kernel(const float* __restrict__ x,
                               const float* __restrict__ noise_var,
                               const float* __restrict__ noise_bias,
                               float* __restrict__ out) {
    __shared__ float tile[TILE_H][TILE_STRIDE];

    const int b   = blockIdx.y;
    const int rb  = blockIdx.x * RPB;
    const int tid = threadIdx.y * TX + threadIdx.x;
    const float* __restrict__ xb_ptr = x + (size_t)b * HH * WW;

    // zero-padded tile load: 12 rows x 516 cols, striped over 256 threads
#pragma unroll
    for (int r = 0; r < TILE_H; r++) {
        const int gr = rb - 2 + r;
        const bool rok = (unsigned)gr < HH;
        const float* __restrict__ src = xb_ptr + (size_t)gr * WW;
#pragma unroll
        for (int cc = 0; cc < 3; cc++) {
            int c = tid + cc * NTHREADS;
            if (c < TILE_W) {
                int gc = c - 2;
                tile[r][c] = (rok && (unsigned)gc < WW) ? src[gc] : 0.0f;
            }
        }
    }
    __syncthreads();

    const float nv = noise_var[0];
    const float nb = noise_bias[0];

    const int ty    = threadIdx.y;
    const int xbase = threadIdx.x * PXT;

    // Rotating live state
    float Ecur[5], Enext[5], C3[5];   // sorted columns 2t, 2t+2, 2t+3
    float M[10];                      // merge of columns 2t+1, 2t+2
    float sM, qM, s3, q3;             // sums for M-cols pair and col 2t+3
    float sE0, qE0, sE1, qE1;         // sum/sq queue for E columns (2t, 2t+2)
    float cenE, cenO;

    // ---- prologue: columns 0..3 ----
    {
        float c0[5], c1[5], c2[5], c3v[5];
#pragma unroll
        for (int jp = 0; jp < 2; jp++) {
#pragma unroll
            for (int k = 0; k < 5; k++) {
                float2 gg = *(const float2*)&tile[ty + k][xbase + 2 * jp];
                (jp ? c2 : c0)[k]  = gg.x;
                (jp ? c3v : c1)[k] = gg.y;
            }
        }
        sE0  = sum5(c0);             qE0 = sq5(c0);
        sE1  = sum5(c2);             qE1 = sq5(c2);
        sM   = sum5(c1) + sE1;       qM  = sq5(c1) + qE1;
        s3   = sum5(c3v);            q3  = sq5(c3v);
        cenE = c2[2];
        cenO = c3v[2];
        sort5(c0); sort5(c1); sort5(c2); sort5(c3v);
#pragma unroll
        for (int k = 0; k < 5; k++) { Ecur[k] = c0[k]; Enext[k] = c2[k]; C3[k] = c3v[k]; }
        merge55(c1, c2, M);
    }

    float2* __restrict__ orow =
        (float2*)(out + (size_t)b * HH * WW + (size_t)(rb + ty) * WW + xbase);

#pragma unroll
    for (int t = 0; t < PXT / 2; t++) {
        // fresh columns 2t+4, 2t+5
        float v4[5], v5[5];
#pragma unroll
        for (int k = 0; k < 5; k++) {
            float2 gg = *(const float2*)&tile[ty + k][xbase + 2 * t + 4];
            v4[k] = gg.x;
            v5[k] = gg.y;
        }
        float s4 = sum5(v4), q4 = sq5(v4);
        float s5 = sum5(v5), q5 = sq5(v5);
        float cen4 = v4[2], cen5 = v5[2];
        sort5(v4); sort5(v5);

        float N[10];                   // merge(col 2t+3, col 2t+4) = next M
        merge55(C3, v4, N);

        float s[6];
        prune_mid(M, N, s);

        float sN = s3 + s4;
        float qN = q3 + q4;

        // even pixel p = 2t: window = E(2t) + M-cols + N-cols
        float sum_e = sE0 + sM + sN;
        float sq_e  = qE0 + qM + qN;
        float var_e = fmaxf((sq_e - sum_e * sum_e * 0.04f) * (1.0f / 24.0f), 0.0f);
        float med_e = sel13(s, Ecur);
        float y_e   = cenE - nv * __fdividef(cenE - med_e + nb, var_e + 1e-10f);

        // odd pixel p = 2t+1: window = M-cols + N-cols + col(2t+5)
        float sum_o = sM + sN + s5;
        float sq_o  = qM + qN + q5;
        float var_o = fmaxf((sq_o - sum_o * sum_o * 0.04f) * (1.0f / 24.0f), 0.0f);
        float med_o = sel13(s, v5);
        float y_o   = cenO - nv * __fdividef(cenO - med_o + nb, var_o + 1e-10f);

        orow[t] = make_float2(fmaxf(y_e, 0.0f), fmaxf(y_o, 0.0f));

        // rotate state for pair t+1
#pragma unroll
        for (int k = 0; k < 5; k++) { Ecur[k] = Enext[k]; Enext[k] = v4[k]; C3[k] = v5[k]; }
#pragma unroll
        for (int k = 0; k < 10; k++) M[k] = N[k];
        sM = sN; qM = qN;
        s3 = s5; q3 = q5;
        sE0 = sE1; qE0 = qE1;
        sE1 = s4;  qE1 = q4;
        cenE = cen4; cenO = cen5;
    }
}

extern "C" void kernel_launch(void* const* d_in, const int* in_sizes, int n_in,
                              void* d_out, int out_size) {
    const float* x  = (const float*)d_in[0];
    const float* nv = (const float*)d_in[1];
    const float* nb = (const float*)d_in[2];
    float* out = (float*)d_out;

    dim3 block(TX, RPB);
    dim3 grid(HH / RPB, BATCH);
    Net_29291676958726_kernel<<<grid, block>>>(x, nv, nb, out);
}

// round 10
// speedup vs baseline: 1.0281x; 1.0281x over previous
#include <cuda_runtime.h>

#define HH 512
#define WW 512
#define BATCH 16
#define RPB 8        // rows per block (= threadIdx.y range)
#define PXT 16       // pixels per thread along x
#define TX 32        // threads in x (TX*PXT = 512)
#define TILE_W 516   // 512 + 2 halo each side
#define TILE_STRIDE 520
#define TILE_H (RPB + 4)      // 12
#define NTHREADS (TX * RPB)   // 256
#define SLOT_WORDS 15         // 2 slots x 7 floats + 1 pad (15 coprime 32 -> conflict-free)

__device__ __forceinline__ void ce(float& a, float& b) {
    float t = fminf(a, b);
    b = fmaxf(a, b);
    a = t;
}

// optimal 9-CE sorting network for 5 elements
__device__ __forceinline__ void sort5(float v[5]) {
    ce(v[0], v[1]); ce(v[3], v[4]); ce(v[2], v[4]);
    ce(v[2], v[3]); ce(v[0], v[3]); ce(v[0], v[2]);
    ce(v[1], v[4]); ce(v[1], v[3]); ce(v[1], v[2]);
}

// Batcher odd-even merge of two sorted 5-lists -> sorted 10-list (13 CE)
__device__ __forceinline__ void merge55(const float x[5], const float y[5], float z[10]) {
    float t0 = fminf(x[0], y[0]), t1 = fmaxf(x[0], y[0]);
    float w0 = fminf(x[4], y[4]), w1 = fmaxf(x[4], y[4]);
    float r1 = fminf(w0, t1),     r2 = fmaxf(w0, t1);
    float s0 = fminf(x[2], y[2]), s1 = fmaxf(x[2], y[2]);
    float p0 = t0;
    float p1 = fminf(s0, r1), p2 = fmaxf(s0, r1);
    float p3 = fminf(s1, r2), p4 = fmaxf(s1, r2);
    float p5 = w1;
    float a0 = fminf(x[1], y[1]), a1 = fmaxf(x[1], y[1]);
    float b0 = fminf(x[3], y[3]), b1 = fmaxf(x[3], y[3]);
    float q0 = a0;
    float q1 = fminf(b0, a1), q2 = fmaxf(b0, a1);
    float q3 = b1;
    z[0] = p0;
    z[1] = fminf(q0, p1); z[2] = fmaxf(q0, p1);
    z[3] = fminf(q1, p2); z[4] = fmaxf(q1, p2);
    z[5] = fminf(q2, p3); z[6] = fmaxf(q2, p3);
    z[7] = fminf(q3, p4); z[8] = fmaxf(q3, p4);
    z[9] = p5;
}

// Pruned OEM(10,10): ranks 7..12 (s[0]=s7 ... s[5]=s12) of the merged 20-list.
__device__ __forceinline__ void prune_mid(const float m1[10], const float m2[10], float s[6]) {
    float t1  = fmaxf(m1[0], m2[0]);
    float w0  = fminf(m1[8], m2[8]);
    float r1  = fminf(w0, t1),  r2 = fmaxf(w0, t1);
    float s0  = fminf(m1[4], m2[4]), s1 = fmaxf(m1[4], m2[4]);
    float p2  = fmaxf(s0, r1),  p3 = fminf(s1, r2);
    float t1q = fmaxf(m1[2], m2[2]);
    float w0q = fminf(m1[6], m2[6]);
    float q1  = fminf(w0q, t1q), q2 = fmaxf(w0q, t1q);
    float d4  = fmaxf(q1, p2);
    float d5  = fminf(q2, p3), d6 = fmaxf(q2, p3);

    float t1g = fmaxf(m1[1], m2[1]);
    float w0g = fminf(m1[9], m2[9]);
    float r1g = fminf(w0g, t1g), r2g = fmaxf(w0g, t1g);
    float s0g = fminf(m1[5], m2[5]), s1g = fmaxf(m1[5], m2[5]);
    float p2g = fmaxf(s0g, r1g), p3g = fminf(s1g, r2g);
    float t1h = fmaxf(m1[3], m2[3]);
    float w0h = fminf(m1[7], m2[7]);
    float q1g = fminf(w0h, t1h), q2g = fmaxf(w0h, t1h);
    float g3  = fminf(q1g, p2g), g4 = fmaxf(q1g, p2g);
    float g5  = fminf(q2g, p3g);

    s[0] = fminf(g3, d4); s[1] = fmaxf(g3, d4);
    s[2] = fminf(g4, d5); s[3] = fmaxf(g4, d5);
    s[4] = fminf(g5, d6); s[5] = fmaxf(g5, d6);
}

// 13th smallest of S(20) U E(5), tree-shaped.
__device__ __forceinline__ float sel13(const float s[6], const float E[5]) {
    float a = fmaxf(s[4], E[0]);
    float b = fmaxf(s[3], E[1]);
    float c = fmaxf(s[2], E[2]);
    float d = fmaxf(s[1], E[3]);
    float e = fmaxf(s[0], E[4]);
    return fminf(fminf(fminf(a, b), fminf(c, d)), fminf(e, s[5]));
}

__device__ __forceinline__ float sum5(const float v[5]) {
    return ((v[0] + v[1]) + (v[2] + v[3])) + v[4];
}
__device__ __forceinline__ float sq5(const float v[5]) {
    return fmaf(v[0], v[0], fmaf(v[1], v[1], fmaf(v[2], v[2], fmaf(v[3], v[3], v[4] * v[4]))));
}

__global__ __launch_bounds__(NTHREADS, 4)
void Net_29291676958726_kernel(const float* __restrict__ x,
                               const float* __restrict__ noise_var,
                               const float* __restrict__ noise_bias,
                               float* __restrict__ out) {
    __shared__ float tile[TILE_H][TILE_STRIDE];          // ~25 KB
    __shared__ float dline[NTHREADS * SLOT_WORDS];       // ~15.4 KB, conflict-free per-thread slots

    const int b   = blockIdx.y;
    const int rb  = blockIdx.x * RPB;
    const int tid = threadIdx.y * TX + threadIdx.x;
    const float* __restrict__ xb_ptr = x + (size_t)b * HH * WW;

    // zero-padded tile load: 12 rows x 516 cols, striped over 256 threads
#pragma unroll
    for (int r = 0; r < TILE_H; r++) {
        const int gr = rb - 2 + r;
        const bool rok = (unsigned)gr < HH;
        const float* __restrict__ src = xb_ptr + (size_t)gr * WW;
#pragma unroll
        for (int cc = 0; cc < 3; cc++) {
            int c = tid + cc * NTHREADS;
            if (c < TILE_W) {
                int gc = c - 2;
                tile[r][c] = (rok && (unsigned)gc < WW) ? src[gc] : 0.0f;
            }
        }
    }
    __syncthreads();

    const float nv = noise_var[0];
    const float nb = noise_bias[0];

    const int ty    = threadIdx.y;
    const int xbase = threadIdx.x * PXT;
    float* __restrict__ slot = &dline[tid * SLOT_WORDS];

    // Loop-carried register state (small by design):
    float C3[5];            // sorted col 2t+3
    float M[10];            // merge of cols 2t+1, 2t+2
    float sM, qM, s3, q3;   // sums for M pair and col 2t+3
    float cen4p, cen5p;     // centers of cols 2t+2, 2t+3

    // ---- prologue: columns 0..3 ----
    {
        float c0[5], c1[5], c2[5], c3v[5];
#pragma unroll
        for (int jp = 0; jp < 2; jp++) {
#pragma unroll
            for (int k = 0; k < 5; k++) {
                float2 gg = *(const float2*)&tile[ty + k][xbase + 2 * jp];
                (jp ? c2 : c0)[k]  = gg.x;
                (jp ? c3v : c1)[k] = gg.y;
            }
        }
        float s0 = sum5(c0), q0 = sq5(c0);
        float s2 = sum5(c2), q2 = sq5(c2);
        sM = sum5(c1) + s2;  qM = sq5(c1) + q2;
        s3 = sum5(c3v);      q3 = sq5(c3v);
        cen4p = c2[2];
        cen5p = c3v[2];
        sort5(c0); sort5(c1); sort5(c2); sort5(c3v);
        // delay-line: slot0 <- col0 (read at pair 0), slot1 <- col2 (read at pair 1)
#pragma unroll
        for (int k = 0; k < 5; k++) { slot[k] = c0[k]; slot[7 + k] = c2[k]; }
        slot[5]  = s0; slot[6]  = q0;
        slot[12] = s2; slot[13] = q2;
#pragma unroll
        for (int k = 0; k < 5; k++) C3[k] = c3v[k];
        merge55(c1, c2, M);
    }

    float2* __restrict__ orow =
        (float2*)(out + (size_t)b * HH * WW + (size_t)(rb + ty) * WW + xbase);

#pragma unroll
    for (int t = 0; t < PXT / 2; t++) {
        const int sl = (t & 1) ? 7 : 0;

        // E column (col 2t) + its sums from the delay-line (conflict-free LDS)
        float E[5];
#pragma unroll
        for (int k = 0; k < 5; k++) E[k] = slot[sl + k];
        float sE = slot[sl + 5];
        float qE = slot[sl + 6];

        // fresh columns 2t+4, 2t+5
        float v4[5], v5[5];
#pragma unroll
        for (int k = 0; k < 5; k++) {
            float2 gg = *(const float2*)&tile[ty + k][xbase + 2 * t + 4];
            v4[k] = gg.x;
            v5[k] = gg.y;
        }
        float s4 = sum5(v4), q4 = sq5(v4);
        float s5 = sum5(v5), q5 = sq5(v5);
        float cen4 = v4[2], cen5 = v5[2];
        sort5(v4); sort5(v5);

        // push col 2t+4 into the delay-line (read again at pair t+2 as E)
#pragma unroll
        for (int k = 0; k < 5; k++) slot[sl + k] = v4[k];
        slot[sl + 5] = s4; slot[sl + 6] = q4;

        float N[10];                   // merge(col 2t+3, col 2t+4) = next M
        merge55(C3, v4, N);

        float s[6];
        prune_mid(M, N, s);

        float sN = s3 + s4;
        float qN = q3 + q4;

        // even pixel p = 2t: window = E(2t) + M-cols + N-cols
        float sum_e = sE + sM + sN;
        float sq_e  = qE + qM + qN;
        float var_e = fmaxf((sq_e - sum_e * sum_e * 0.04f) * (1.0f / 24.0f), 0.0f);
        float med_e = sel13(s, E);
        float y_e   = cen4p - nv * __fdividef(cen4p - med_e + nb, var_e + 1e-10f);

        // odd pixel p = 2t+1: window = M-cols + N-cols + col(2t+5)
        float sum_o = sM + sN + s5;
        float sq_o  = qM + qN + q5;
        float var_o = fmaxf((sq_o - sum_o * sum_o * 0.04f) * (1.0f / 24.0f), 0.0f);
        float med_o = sel13(s, v5);
        float y_o   = cen5p - nv * __fdividef(cen5p - med_o + nb, var_o + 1e-10f);

        orow[t] = make_float2(fmaxf(y_e, 0.0f), fmaxf(y_o, 0.0f));

        // rotate register state for pair t+1
#pragma unroll
        for (int k = 0; k < 5; k++) C3[k] = v5[k];
#pragma unroll
        for (int k = 0; k < 10; k++) M[k] = N[k];
        sM = sN; qM = qN;
        s3 = s5; q3 = q5;
        cen4p = cen4; cen5p = cen5;
    }
}

extern "C" void kernel_launch(void* const* d_in, const int* in_sizes, int n_in,
                              void* d_out, int out_size) {
    const float* x  = (const float*)d_in[0];
    const float* nv = (const float*)d_in[1];
    const float* nb = (const float*)d_in[2];
    float* out = (float*)d_out;

    dim3 block(TX, RPB);
    dim3 grid(HH / RPB, BATCH);
    Net_29291676958726_kernel<<<grid, block>>>(x, nv, nb, out);
}

// round 11
// speedup vs baseline: 1.1765x; 1.1443x over previous
#include <cuda_runtime.h>

#define HH 512
#define WW 512
#define BATCH 16
#define RPB 8        // rows per block (= threadIdx.y range)
#define PXT 16       // pixels per thread along x
#define TX 32        // threads in x (TX*PXT = 512)
#define TILE_W 516   // 512 + 2 halo each side
#define TILE_H (RPB + 4)      // 12
#define NTHREADS (TX * RPB)   // 256
// padded row: 2 pad words after every 16 columns -> word index = x + (x>>4)*2
#define ROWW 584              // > 515 + 64 = 579, padded row stride in words

__device__ __forceinline__ void ce(float& a, float& b) {
    float t = fminf(a, b);
    b = fmaxf(a, b);
    a = t;
}

// optimal 9-CE sorting network for 5 elements
__device__ __forceinline__ void sort5(float v[5]) {
    ce(v[0], v[1]); ce(v[3], v[4]); ce(v[2], v[4]);
    ce(v[2], v[3]); ce(v[0], v[3]); ce(v[0], v[2]);
    ce(v[1], v[4]); ce(v[1], v[3]); ce(v[1], v[2]);
}

// Batcher odd-even merge of two sorted 5-lists -> sorted 10-list (13 CE)
__device__ __forceinline__ void merge55(const float x[5], const float y[5], float z[10]) {
    float t0 = fminf(x[0], y[0]), t1 = fmaxf(x[0], y[0]);
    float w0 = fminf(x[4], y[4]), w1 = fmaxf(x[4], y[4]);
    float r1 = fminf(w0, t1),     r2 = fmaxf(w0, t1);
    float s0 = fminf(x[2], y[2]), s1 = fmaxf(x[2], y[2]);
    float p0 = t0;
    float p1 = fminf(s0, r1), p2 = fmaxf(s0, r1);
    float p3 = fminf(s1, r2), p4 = fmaxf(s1, r2);
    float p5 = w1;
    float a0 = fminf(x[1], y[1]), a1 = fmaxf(x[1], y[1]);
    float b0 = fminf(x[3], y[3]), b1 = fmaxf(x[3], y[3]);
    float q0 = a0;
    float q1 = fminf(b0, a1), q2 = fmaxf(b0, a1);
    float q3 = b1;
    z[0] = p0;
    z[1] = fminf(q0, p1); z[2] = fmaxf(q0, p1);
    z[3] = fminf(q1, p2); z[4] = fmaxf(q1, p2);
    z[5] = fminf(q2, p3); z[6] = fmaxf(q2, p3);
    z[7] = fminf(q3, p4); z[8] = fmaxf(q3, p4);
    z[9] = p5;
}

// Pruned OEM(10,10): ranks 7..12 (s[0]=s7 ... s[5]=s12) of the merged 20-list.
__device__ __forceinline__ void prune_mid(const float m1[10], const float m2[10], float s[6]) {
    float t1  = fmaxf(m1[0], m2[0]);
    float w0  = fminf(m1[8], m2[8]);
    float r1  = fminf(w0, t1),  r2 = fmaxf(w0, t1);
    float s0  = fminf(m1[4], m2[4]), s1 = fmaxf(m1[4], m2[4]);
    float p2  = fmaxf(s0, r1),  p3 = fminf(s1, r2);
    float t1q = fmaxf(m1[2], m2[2]);
    float w0q = fminf(m1[6], m2[6]);
    float q1  = fminf(w0q, t1q), q2 = fmaxf(w0q, t1q);
    float d4  = fmaxf(q1, p2);
    float d5  = fminf(q2, p3), d6 = fmaxf(q2, p3);

    float t1g = fmaxf(m1[1], m2[1]);
    float w0g = fminf(m1[9], m2[9]);
    float r1g = fminf(w0g, t1g), r2g = fmaxf(w0g, t1g);
    float s0g = fminf(m1[5], m2[5]), s1g = fmaxf(m1[5], m2[5]);
    float p2g = fmaxf(s0g, r1g), p3g = fminf(s1g, r2g);
    float t1h = fmaxf(m1[3], m2[3]);
    float w0h = fminf(m1[7], m2[7]);
    float q1g = fminf(w0h, t1h), q2g = fmaxf(w0h, t1h);
    float g3  = fminf(q1g, p2g), g4 = fmaxf(q1g, p2g);
    float g5  = fminf(q2g, p3g);

    s[0] = fminf(g3, d4); s[1] = fmaxf(g3, d4);
    s[2] = fminf(g4, d5); s[3] = fmaxf(g4, d5);
    s[4] = fminf(g5, d6); s[5] = fmaxf(g5, d6);
}

// 13th smallest of S(20) U E(5), tree-shaped.
__device__ __forceinline__ float sel13(const float s[6], const float E[5]) {
    float a = fmaxf(s[4], E[0]);
    float b = fmaxf(s[3], E[1]);
    float c = fmaxf(s[2], E[2]);
    float d = fmaxf(s[1], E[3]);
    float e = fmaxf(s[0], E[4]);
    return fminf(fminf(fminf(a, b), fminf(c, d)), fminf(e, s[5]));
}

__device__ __forceinline__ float sum5(const float v[5]) {
    return ((v[0] + v[1]) + (v[2] + v[3])) + v[4];
}
__device__ __forceinline__ float sq5(const float v[5]) {
    return fmaf(v[0], v[0], fmaf(v[1], v[1], fmaf(v[2], v[2], fmaf(v[3], v[3], v[4] * v[4]))));
}

__global__ __launch_bounds__(NTHREADS, 4)
void Net_29291676958726_kernel(const float* __restrict__ x,
                               const float* __restrict__ noise_var,
                               const float* __restrict__ noise_bias,
                               float* __restrict__ out) {
    __shared__ float tile[TILE_H * ROWW];   // padded: word idx = r*ROWW + x + (x>>4)*2

    const int b   = blockIdx.y;
    const int rb  = blockIdx.x * RPB;
    const int tid = threadIdx.y * TX + threadIdx.x;
    const float* __restrict__ xb_ptr = x + (size_t)b * HH * WW;

    // zero-padded tile load into padded layout
#pragma unroll
    for (int r = 0; r < TILE_H; r++) {
        const int gr = rb - 2 + r;
        const bool rok = (unsigned)gr < HH;
        const float* __restrict__ src = xb_ptr + (size_t)gr * WW;
#pragma unroll
        for (int cc = 0; cc < 3; cc++) {
            int c = tid + cc * NTHREADS;
            if (c < TILE_W) {
                int gc = c - 2;
                float v = (rok && (unsigned)gc < WW) ? src[gc] : 0.0f;
                tile[r * ROWW + c + ((c >> 4) << 1)] = v;
            }
        }
    }
    __syncthreads();

    const float nv = noise_var[0];
    const float nb = noise_bias[0];

    const int ty = threadIdx.y;
    // thread base: x = 16*tx starts exactly at pad-group tx -> word offset 18*tx
    const float* __restrict__ tbase = &tile[ty * ROWW + 18 * threadIdx.x];
    // column j (0..19) of this thread at row k: tbase[k*ROWW + j + (j>=16 ? 2 : 0)]
#define TCOL(k, j) (tbase[(k) * ROWW + (j) + (((j) >= 16) ? 2 : 0)])

    // Rotating live state
    float Ecur[5], Enext[5], C3[5];   // sorted columns 2t, 2t+2, 2t+3
    float M[10];                      // merge of columns 2t+1, 2t+2
    float sM, qM, s3, q3;             // sums for M-cols pair and col 2t+3
    float sE0, qE0, sE1, qE1;         // sum/sq queue for E columns (2t, 2t+2)
    float cenE, cenO;

    // ---- prologue: columns 0..3 ----
    {
        float c0[5], c1[5], c2[5], c3v[5];
#pragma unroll
        for (int k = 0; k < 5; k++) {
            float2 g0 = *(const float2*)&TCOL(k, 0);
            float2 g1 = *(const float2*)&TCOL(k, 2);
            c0[k]  = g0.x; c1[k] = g0.y;
            c2[k]  = g1.x; c3v[k] = g1.y;
        }
        sE0  = sum5(c0);             qE0 = sq5(c0);
        sE1  = sum5(c2);             qE1 = sq5(c2);
        sM   = sum5(c1) + sE1;       qM  = sq5(c1) + qE1;
        s3   = sum5(c3v);            q3  = sq5(c3v);
        cenE = c2[2];
        cenO = c3v[2];
        sort5(c0); sort5(c1); sort5(c2); sort5(c3v);
#pragma unroll
        for (int k = 0; k < 5; k++) { Ecur[k] = c0[k]; Enext[k] = c2[k]; C3[k] = c3v[k]; }
        merge55(c1, c2, M);
    }

    float2* __restrict__ orow =
        (float2*)(out + (size_t)b * HH * WW + (size_t)(rb + ty) * WW + threadIdx.x * PXT);

#pragma unroll
    for (int t = 0; t < PXT / 2; t++) {
        // fresh columns 2t+4, 2t+5 (2-way-conflict-max float2 LDS)
        float v4[5], v5[5];
#pragma unroll
        for (int k = 0; k < 5; k++) {
            float2 gg = *(const float2*)&TCOL(k, 2 * t + 4);
            v4[k] = gg.x;
            v5[k] = gg.y;
        }
        float s4 = sum5(v4), q4 = sq5(v4);
        float s5 = sum5(v5), q5 = sq5(v5);
        float cen4 = v4[2], cen5 = v5[2];
        sort5(v4); sort5(v5);

        float N[10];                   // merge(col 2t+3, col 2t+4) = next M
        merge55(C3, v4, N);

        float s[6];
        prune_mid(M, N, s);

        float sN = s3 + s4;
        float qN = q3 + q4;

        // even pixel p = 2t: window = E(2t) + M-cols + N-cols
        float sum_e = sE0 + sM + sN;
        float sq_e  = qE0 + qM + qN;
        float var_e = fmaxf((sq_e - sum_e * sum_e * 0.04f) * (1.0f / 24.0f), 0.0f);
        float med_e = sel13(s, Ecur);
        float y_e   = cenE - nv * __fdividef(cenE - med_e + nb, var_e + 1e-10f);

        // odd pixel p = 2t+1: window = M-cols + N-cols + col(2t+5)
        float sum_o = sM + sN + s5;
        float sq_o  = qM + qN + q5;
        float var_o = fmaxf((sq_o - sum_o * sum_o * 0.04f) * (1.0f / 24.0f), 0.0f);
        float med_o = sel13(s, v5);
        float y_o   = cenO - nv * __fdividef(cenO - med_o + nb, var_o + 1e-10f);

        orow[t] = make_float2(fmaxf(y_e, 0.0f), fmaxf(y_o, 0.0f));

        // rotate state for pair t+1
#pragma unroll
        for (int k = 0; k < 5; k++) { Ecur[k] = Enext[k]; Enext[k] = v4[k]; C3[k] = v5[k]; }
#pragma unroll
        for (int k = 0; k < 10; k++) M[k] = N[k];
        sM = sN; qM = qN;
        s3 = s5; q3 = q5;
        sE0 = sE1; qE0 = qE1;
        sE1 = s4;  qE1 = q4;
        cenE = cen4; cenO = cen5;
    }
#undef TCOL
}

extern "C" void kernel_launch(void* const* d_in, const int* in_sizes, int n_in,
                              void* d_out, int out_size) {
    const float* x  = (const float*)d_in[0];
    const float* nv = (const float*)d_in[1];
    const float* nb = (const float*)d_in[2];
    float* out = (float*)d_out;

    dim3 block(TX, RPB);
    dim3 grid(HH / RPB, BATCH);
    Net_29291676958726_kernel<<<grid, block>>>(x, nv, nb, out);
}